// round 1
// baseline (speedup 1.0000x reference)
#include <cuda_runtime.h>

// Problem constants
#define B_    64
#define T_    256
#define I_    512
#define O_    512
#define NOBS  128
#define ETA   0.01f

// Tiling: 16 warps/CTA, 4 rows/warp -> 64 rows/CTA, 8 CTAs per batch element.
#define WARPS   16
#define RPW     4
#define ROWS    (WARPS * RPW)      // 64
#define CHUNKS  (O_ / ROWS)        // 8
#define THREADS (WARPS * 32)       // 512
#define GRID    (B_ * CHUNKS)      // 512

typedef unsigned long long u64;

// ---- packed f32x2 helpers (Blackwell sm_100+) ----
__device__ __forceinline__ u64 pack2(float x, float y) {
    u64 r;
    asm("mov.b64 %0, {%1, %2};" : "=l"(r) : "f"(x), "f"(y));
    return r;
}
__device__ __forceinline__ void unpack2(u64 v, float& x, float& y) {
    asm("mov.b64 {%0, %1}, %2;" : "=f"(x), "=f"(y) : "l"(v));
}
__device__ __forceinline__ u64 ffma2(u64 a, u64 b, u64 c) {
    u64 d;
    asm("fma.rn.f32x2 %0, %1, %2, %3;" : "=l"(d) : "l"(a), "l"(b), "l"(c));
    return d;
}
__device__ __forceinline__ u64 fmul2(u64 a, u64 b) {
    u64 d;
    asm("mul.rn.f32x2 %0, %1, %2;" : "=l"(d) : "l"(a), "l"(b));
    return d;
}
__device__ __forceinline__ u64 fadd2(u64 a, u64 b) {
    u64 d;
    asm("add.rn.f32x2 %0, %1, %2;" : "=l"(d) : "l"(a), "l"(b));
    return d;
}

__global__ void __launch_bounds__(THREADS, 1)
circuit_kernel(const float* __restrict__ X,
               const float* __restrict__ Winit,
               const int*   __restrict__ obs,
               float*       __restrict__ out)
{
    __shared__ float y_s[ROWS];
    __shared__ int   obs_s[NOBS];

    const int b    = blockIdx.x / CHUNKS;
    const int row0 = (blockIdx.x % CHUNKS) * ROWS;
    const int tid  = threadIdx.x;
    const int w    = tid >> 5;
    const int l    = tid & 31;

    if (tid < NOBS) obs_s[tid] = obs[tid];

    // Load this warp's 4 W rows into registers.
    // Lane l owns contiguous elements [16*l, 16*l+16) of each row -> float4 coalesced.
    u64 wr[RPW][8];
    #pragma unroll
    for (int r = 0; r < RPW; r++) {
        const int o = row0 + w * RPW + r;
        const float4* p = reinterpret_cast<const float4*>(
            Winit + ((size_t)b * O_ + o) * I_ + l * 16);
        #pragma unroll
        for (int q = 0; q < 4; q++) {
            float4 v = p[q];
            wr[r][2 * q]     = pack2(v.x, v.y);
            wr[r][2 * q + 1] = pack2(v.z, v.w);
        }
    }
    __syncthreads();  // obs_s visible

    const float* Xb   = X + (size_t)b * T_ * I_;
    float*       outb = out + (size_t)b * T_ * NOBS;

    for (int t = 0; t < T_; t++) {
        // Load x_t slice for this lane (same for all warps; L1 broadcast-hit).
        u64 xv[8];
        {
            const float4* xp = reinterpret_cast<const float4*>(Xb + t * I_ + l * 16);
            #pragma unroll
            for (int q = 0; q < 4; q++) {
                float4 v = xp[q];
                xv[2 * q]     = pack2(v.x, v.y);
                xv[2 * q + 1] = pack2(v.z, v.w);
            }
        }

        #pragma unroll
        for (int r = 0; r < RPW; r++) {
            // dot(W_row, x) with 2 accumulators for ILP
            u64 acc0 = pack2(0.f, 0.f);
            u64 acc1 = pack2(0.f, 0.f);
            #pragma unroll
            for (int k = 0; k < 8; k += 2) {
                acc0 = ffma2(wr[r][k],     xv[k],     acc0);
                acc1 = ffma2(wr[r][k + 1], xv[k + 1], acc1);
            }
            u64 acc = fadd2(acc0, acc1);
            float ax, ay;
            unpack2(acc, ax, ay);
            float s = ax + ay;
            // warp reduce-all (every lane ends with the full sum)
            #pragma unroll
            for (int off = 16; off > 0; off >>= 1)
                s += __shfl_xor_sync(0xffffffffu, s, off);

            const float y = 1.0f / (1.0f + __expf(-s));

            if (l == r) y_s[w * RPW + r] = y;   // stage for observed gather

            const float c1 = 1.0f - ETA * y * y;   // decay
            const float c2 = ETA * y;              // hebbian gain
            const u64 c1c1 = pack2(c1, c1);
            const u64 c2c2 = pack2(c2, c2);
            #pragma unroll
            for (int k = 0; k < 8; k++)
                wr[r][k] = ffma2(c1c1, wr[r][k], fmul2(c2c2, xv[k]));
        }

        __syncthreads();
        if (tid < NOBS) {
            const int o = obs_s[tid] - row0;
            if ((unsigned)o < (unsigned)ROWS)
                outb[t * NOBS + tid] = y_s[o];
        }
        __syncthreads();  // protect y_s before next step overwrites
    }
}

extern "C" void kernel_launch(void* const* d_in, const int* in_sizes, int n_in,
                              void* d_out, int out_size)
{
    const float* X  = (const float*)d_in[0];   // (B, T, I) f32
    const float* Wi = (const float*)d_in[1];   // (B, O, I) f32
    const int* obs  = (const int*)d_in[2];     // (NOBS,) i32
    float* out      = (float*)d_out;           // (B, T, NOBS) f32

    circuit_kernel<<<GRID, THREADS>>>(X, Wi, obs, out);
}

// round 2
// speedup vs baseline: 1.8095x; 1.8095x over previous
#include <cuda_runtime.h>

// Problem constants
#define B_    64
#define T_    256
#define I_    512
#define O_    512
#define NOBS  128
#define ETA   0.01f

// Tiling: 16 warps/CTA, 4 rows/warp -> 64 rows/CTA, 8 CTAs per batch element.
#define WARPS   16
#define RPW     4
#define ROWS    (WARPS * RPW)      // 64
#define CHUNKS  (O_ / ROWS)        // 8
#define THREADS (WARPS * 32)       // 512
#define GRID    (B_ * CHUNKS)      // 512

typedef unsigned long long u64;
#define FULLM 0xffffffffu

// ---- packed f32x2 helpers (Blackwell sm_100+) ----
// Two consecutive little-endian floats in memory == one f32x2 operand,
// so we load u64/ulonglong2 directly and never repack.
__device__ __forceinline__ u64 pack2(float x, float y) {
    u64 r;
    asm("mov.b64 %0, {%1, %2};" : "=l"(r) : "f"(x), "f"(y));
    return r;
}
__device__ __forceinline__ void unpack2(u64 v, float& x, float& y) {
    asm("mov.b64 {%0, %1}, %2;" : "=f"(x), "=f"(y) : "l"(v));
}
__device__ __forceinline__ u64 ffma2(u64 a, u64 b, u64 c) {
    u64 d;
    asm("fma.rn.f32x2 %0, %1, %2, %3;" : "=l"(d) : "l"(a), "l"(b), "l"(c));
    return d;
}
__device__ __forceinline__ u64 fmul2(u64 a, u64 b) {
    u64 d;
    asm("mul.rn.f32x2 %0, %1, %2;" : "=l"(d) : "l"(a), "l"(b));
    return d;
}
__device__ __forceinline__ u64 fadd2(u64 a, u64 b) {
    u64 d;
    asm("add.rn.f32x2 %0, %1, %2;" : "=l"(d) : "l"(a), "l"(b));
    return d;
}

__global__ void __launch_bounds__(THREADS, 1)
circuit_kernel(const float* __restrict__ X,
               const float* __restrict__ Winit,
               const int*   __restrict__ obs,
               float*       __restrict__ out)
{
    const int b    = blockIdx.x / CHUNKS;
    const int row0 = (blockIdx.x % CHUNKS) * ROWS;
    const int tid  = threadIdx.x;
    const int w    = tid >> 5;
    const int l    = tid & 31;
    const int wrow = row0 + w * RPW;          // first row owned by this warp

    // ---- Load this warp's 4 W rows (lane l owns elems [16l,16l+16)) ----
    u64 wr[RPW][8];
    #pragma unroll
    for (int r = 0; r < RPW; r++) {
        const ulonglong2* p = reinterpret_cast<const ulonglong2*>(
            Winit + ((size_t)b * O_ + (wrow + r)) * I_ + l * 16);
        #pragma unroll
        for (int q = 0; q < 4; q++) {
            ulonglong2 v = p[q];
            wr[r][2 * q]     = v.x;
            wr[r][2 * q + 1] = v.y;
        }
    }

    // ---- Precompute observed-gather slots: lane l owns obs positions l,l+32,l+64,l+96.
    // A slot is "mine" iff its row falls in this warp's 4 rows.
    int  pos_[4], rel_[4];
    bool val_[4];
    #pragma unroll
    for (int j = 0; j < 4; j++) {
        const int pos = l + 32 * j;
        const int o   = __ldg(obs + pos);
        const int rel = o - wrow;
        pos_[j] = pos;
        rel_[j] = rel;
        val_[j] = ((unsigned)rel < (unsigned)RPW);
    }

    float* outb = out + (size_t)b * T_ * NOBS;
    const float* xrow = X + (size_t)b * T_ * I_ + l * 16;
    const int rsel = (l >> 2) & 3;            // which row this lane finishes

    #pragma unroll 1
    for (int t = 0; t < T_; t++) {
        // ---- x_t slice for this lane (u64 direct, no repacking) ----
        u64 xv[8];
        {
            const ulonglong2* xp = reinterpret_cast<const ulonglong2*>(xrow);
            #pragma unroll
            for (int q = 0; q < 4; q++) {
                ulonglong2 v = xp[q];
                xv[2 * q]     = v.x;
                xv[2 * q + 1] = v.y;
            }
        }
        xrow += I_;

        // ---- dots: per-lane partial for each of the 4 rows ----
        float s[RPW];
        #pragma unroll
        for (int r = 0; r < RPW; r++) {
            u64 a0 = 0, a1 = 0;               // 0x0 == packed {0.f,0.f}
            #pragma unroll
            for (int k = 0; k < 8; k += 2) {
                a0 = ffma2(wr[r][k],     xv[k],     a0);
                a1 = ffma2(wr[r][k + 1], xv[k + 1], a1);
            }
            float ax, ay, bx, by;
            unpack2(a0, ax, ay);
            unpack2(a1, bx, by);
            s[r] = (ax + bx) + (ay + by);
        }

        // ---- shared 4-row reduction ----
        // 3 packed butterfly levels (off 16/8/4): each lane ends with the
        // partial of all 4 rows summed over lanes sharing l&3.
        u64 P01 = pack2(s[0], s[1]);
        u64 P23 = pack2(s[2], s[3]);
        #pragma unroll
        for (int off = 16; off >= 4; off >>= 1) {
            P01 = fadd2(P01, __shfl_xor_sync(FULLM, P01, off));
            P23 = fadd2(P23, __shfl_xor_sync(FULLM, P23, off));
        }
        float a0, a1, a2, a3;
        unpack2(P01, a0, a1);
        unpack2(P23, a2, a3);
        // lane group g=(l>>2)&3 finishes row g: its 4 lanes hold the 4
        // class-partials of every row; pick row g, reduce over bits 0,1.
        float v = (rsel < 2) ? (rsel == 0 ? a0 : a1)
                             : (rsel == 2 ? a2 : a3);
        v += __shfl_xor_sync(FULLM, v, 1);
        v += __shfl_xor_sync(FULLM, v, 2);

        // one sigmoid per lane (instead of 4)
        const float y = 1.0f / (1.0f + __expf(-v));

        // broadcast: row r's y lives in lane 4r (and copies)
        float yv[RPW];
        #pragma unroll
        for (int r = 0; r < RPW; r++)
            yv[r] = __shfl_sync(FULLM, y, 4 * r);

        // ---- W update: w = (1 - eta*y^2)*w + (eta*y)*x ----
        #pragma unroll
        for (int r = 0; r < RPW; r++) {
            const float c1 = 1.0f - ETA * yv[r] * yv[r];
            const float c2 = ETA * yv[r];
            const u64 c1p = pack2(c1, c1);
            const u64 c2p = pack2(c2, c2);
            #pragma unroll
            for (int k = 0; k < 8; k++)
                wr[r][k] = ffma2(c1p, wr[r][k], fmul2(c2p, xv[k]));
        }

        // ---- observed gather: no smem, no syncs ----
        float* ot = outb + t * NOBS;
        #pragma unroll
        for (int j = 0; j < 4; j++) {
            if (val_[j]) {
                const int r = rel_[j];
                const float yy = (r < 2) ? (r == 0 ? yv[0] : yv[1])
                                         : (r == 2 ? yv[2] : yv[3]);
                ot[pos_[j]] = yy;
            }
        }
    }
}

extern "C" void kernel_launch(void* const* d_in, const int* in_sizes, int n_in,
                              void* d_out, int out_size)
{
    const float* X  = (const float*)d_in[0];   // (B, T, I) f32
    const float* Wi = (const float*)d_in[1];   // (B, O, I) f32
    const int* obs  = (const int*)d_in[2];     // (NOBS,) i32
    float* out      = (float*)d_out;           // (B, T, NOBS) f32

    circuit_kernel<<<GRID, THREADS>>>(X, Wi, obs, out);
}

// round 3
// speedup vs baseline: 2.5611x; 1.4154x over previous
#include <cuda_runtime.h>

#define Bb   64
#define Tt   256
#define Ii   512
#define Oo   512
#define NOBS 128
#define ETA  0.01f
#define CH   32
#define NCH  (Tt / CH)

typedef unsigned long long u64;

// ---- scratch (static __device__, no allocs) ----
__device__ float G_buf[Bb * Tt * Tt];   // G[b][j][t] = x_j . x_t  (upper triangle valid)
__device__ float D_buf[Bb * Tt * Oo];   // D[b][t][o] = W0[b][o] . x_t
__device__ float U_buf[Bb * Tt * Oo];   // u[b][j][o]

// ---- packed f32x2 helpers (sm_100+) ----
__device__ __forceinline__ u64 pack2(float x, float y) {
    u64 r; asm("mov.b64 %0, {%1, %2};" : "=l"(r) : "f"(x), "f"(y)); return r;
}
__device__ __forceinline__ void unpack2(u64 v, float& x, float& y) {
    asm("mov.b64 {%0, %1}, %2;" : "=f"(x), "=f"(y) : "l"(v));
}
__device__ __forceinline__ u64 ffma2(u64 a, u64 b, u64 c) {
    u64 d; asm("fma.rn.f32x2 %0, %1, %2, %3;" : "=l"(d) : "l"(a), "l"(b), "l"(c)); return d;
}

// ============================================================
// Batched NT GEMM: C[b][m][n] = A[b][m][:] . B[b][n][:], K=512
// Tiles 128x128, 256 threads, 8x8 micro via f32x2 (B duplicated in smem).
// TRI: skip tiles strictly below the diagonal (for symmetric G, only j<t used).
// ============================================================
template<int M, int N, bool TRI>
__device__ __forceinline__ void gemm_nt_core(const float* __restrict__ A,
                                             const float* __restrict__ Bm,
                                             float* __restrict__ C)
{
    const int nx = blockIdx.x, my = blockIdx.y, b = blockIdx.z;
    if (TRI && my > nx) return;

    __shared__ __align__(16) float As[16][128];
    __shared__ __align__(16) float Bs[16][256];   // duplicated pairs {b,b}

    const int tid  = threadIdx.x;
    const int ml   = tid & 127;
    const int half = tid >> 7;                    // 0/1 -> k-subrange

    const float* Ag = A  + ((size_t)b * M + my * 128 + ml) * Ii + half * 8;
    const float* Bg = Bm + ((size_t)b * N + nx * 128 + ml) * Ii + half * 8;

    u64 acc[4][8];
    #pragma unroll
    for (int i = 0; i < 4; i++)
        #pragma unroll
        for (int j = 0; j < 8; j++) acc[i][j] = 0;

    const int m0 = (tid & 15) * 8;
    const int n0 = (tid >> 4) * 8;

    float4 pa0 = *(const float4*)(Ag);
    float4 pa1 = *(const float4*)(Ag + 4);
    float4 pb0 = *(const float4*)(Bg);
    float4 pb1 = *(const float4*)(Bg + 4);

    for (int kc = 0; kc < Ii / 16; kc++) {
        __syncthreads();
        {
            const int kb = half * 8;
            As[kb + 0][ml] = pa0.x; As[kb + 1][ml] = pa0.y;
            As[kb + 2][ml] = pa0.z; As[kb + 3][ml] = pa0.w;
            As[kb + 4][ml] = pa1.x; As[kb + 5][ml] = pa1.y;
            As[kb + 6][ml] = pa1.z; As[kb + 7][ml] = pa1.w;
            *(float2*)&Bs[kb + 0][2 * ml] = make_float2(pb0.x, pb0.x);
            *(float2*)&Bs[kb + 1][2 * ml] = make_float2(pb0.y, pb0.y);
            *(float2*)&Bs[kb + 2][2 * ml] = make_float2(pb0.z, pb0.z);
            *(float2*)&Bs[kb + 3][2 * ml] = make_float2(pb0.w, pb0.w);
            *(float2*)&Bs[kb + 4][2 * ml] = make_float2(pb1.x, pb1.x);
            *(float2*)&Bs[kb + 5][2 * ml] = make_float2(pb1.y, pb1.y);
            *(float2*)&Bs[kb + 6][2 * ml] = make_float2(pb1.z, pb1.z);
            *(float2*)&Bs[kb + 7][2 * ml] = make_float2(pb1.w, pb1.w);
        }
        __syncthreads();
        if (kc + 1 < Ii / 16) {
            const float* An = Ag + (kc + 1) * 16;
            const float* Bn = Bg + (kc + 1) * 16;
            pa0 = *(const float4*)(An);
            pa1 = *(const float4*)(An + 4);
            pb0 = *(const float4*)(Bn);
            pb1 = *(const float4*)(Bn + 4);
        }
        #pragma unroll
        for (int k = 0; k < 16; k++) {
            ulonglong2 a01 = *(const ulonglong2*)&As[k][m0];
            ulonglong2 a23 = *(const ulonglong2*)&As[k][m0 + 4];
            ulonglong2 b01 = *(const ulonglong2*)&Bs[k][2 * n0];
            ulonglong2 b23 = *(const ulonglong2*)&Bs[k][2 * n0 + 4];
            ulonglong2 b45 = *(const ulonglong2*)&Bs[k][2 * n0 + 8];
            ulonglong2 b67 = *(const ulonglong2*)&Bs[k][2 * n0 + 12];
            u64 av[4] = {a01.x, a01.y, a23.x, a23.y};
            u64 bv[8] = {b01.x, b01.y, b23.x, b23.y, b45.x, b45.y, b67.x, b67.y};
            #pragma unroll
            for (int i = 0; i < 4; i++)
                #pragma unroll
                for (int j = 0; j < 8; j++)
                    acc[i][j] = ffma2(av[i], bv[j], acc[i][j]);
        }
    }

    #pragma unroll
    for (int i = 0; i < 4; i++)
        #pragma unroll
        for (int j = 0; j < 8; j++) {
            float lo, hi;
            unpack2(acc[i][j], lo, hi);
            const int m = my * 128 + m0 + 2 * i;
            const int n = nx * 128 + n0 + j;
            C[((size_t)b * M + m)     * N + n] = lo;
            C[((size_t)b * M + m + 1) * N + n] = hi;
        }
}

__global__ void __launch_bounds__(256, 2)
gemm_g(const float* __restrict__ X)
{
    gemm_nt_core<Tt, Tt, true>(X, X, G_buf);
}

__global__ void __launch_bounds__(256, 2)
gemm_d(const float* __restrict__ X, const float* __restrict__ W)
{
    gemm_nt_core<Tt, Oo, false>(X, W, D_buf);
}

// ============================================================
// Scan: one thread per (b, o) row.
//   pre_t = P_{t-1} * ( d_t + sum_{j<t} u_j * G[j][t] )
// Chunked by CH=32: history part streams u from U_buf against a
// staged G column-block; intra-chunk part fully unrolled with u in regs.
// ============================================================
__global__ void __launch_bounds__(128, 4)
scan_kernel(const int* __restrict__ obs, float* __restrict__ out)
{
    __shared__ __align__(16) float Gs[Tt * CH];   // [j][tl], j < t0+CH   (32 KB)
    __shared__ float y_s[CH * 128];               // [tl][tid]            (16 KB)

    const int tid  = threadIdx.x;
    const int rg   = blockIdx.x;                  // 0..3 row group
    const int b    = blockIdx.y;                  // 0..63
    const int orow = rg * 128 + tid;

    // observed-slot ownership (slot == tid; exactly one CTA per batch owns it)
    const int  slot_o    = obs[tid];
    const bool have_slot = ((slot_o >> 7) == rg);
    const int  slot_lrow = slot_o & 127;

    const float* Gb   = G_buf + (size_t)b * Tt * Tt;
    const float* Db   = D_buf + (size_t)b * Tt * Oo + orow;
    float*       Ub   = U_buf + (size_t)b * Tt * Oo + orow;
    float*       outb = out   + (size_t)b * Tt * NOBS;

    float P = 1.0f;
    float uc[CH];

    for (int c = 0; c < NCH; c++) {
        const int t0   = c * CH;
        const int rows = t0 + CH;

        __syncthreads();
        // stage Gs[j][tl] = G[b][j][t0+tl] for j < rows (coalesced)
        for (int i = tid; i < rows * CH; i += 128) {
            const int j = i >> 5, tl = i & 31;
            Gs[i] = Gb[j * Tt + t0 + tl];
        }
        __syncthreads();

        // ---- history: H[tl] = sum_{j<t0} u_j * G[j][t0+tl] ----
        u64 hacc[CH / 2];
        #pragma unroll
        for (int q = 0; q < CH / 2; q++) hacc[q] = 0;
        for (int j = 0; j < t0; j++) {
            const float uj = Ub[j * Oo];
            const u64   u2 = pack2(uj, uj);
            const ulonglong2* grow = (const ulonglong2*)&Gs[j * CH];
            #pragma unroll
            for (int q = 0; q < CH / 4; q++) {
                ulonglong2 gg = grow[q];
                hacc[2 * q]     = ffma2(u2, gg.x, hacc[2 * q]);
                hacc[2 * q + 1] = ffma2(u2, gg.y, hacc[2 * q + 1]);
            }
        }
        float H[CH];
        #pragma unroll
        for (int q = 0; q < CH / 2; q++) unpack2(hacc[q], H[2 * q], H[2 * q + 1]);

        // ---- sequential 32 steps (no cross-thread deps) ----
        #pragma unroll
        for (int tl = 0; tl < CH; tl++) {
            float S = H[tl];
            #pragma unroll
            for (int jl = 0; jl < tl; jl++)
                S = fmaf(uc[jl], Gs[(t0 + jl) * CH + tl], S);
            const float d   = Db[(t0 + tl) * Oo];
            const float pre = P * (d + S);
            const float y   = 1.0f / (1.0f + __expf(-pre));
            const float c1  = 1.0f - ETA * y * y;
            P *= c1;
            const float u = __fdividef(ETA * y, P);
            uc[tl] = u;
            Ub[(t0 + tl) * Oo]  = u;
            y_s[tl * 128 + tid] = y;
        }
        __syncthreads();

        if (have_slot) {
            #pragma unroll 4
            for (int tl = 0; tl < CH; tl++)
                outb[(t0 + tl) * NOBS + tid] = y_s[tl * 128 + slot_lrow];
        }
    }
}

extern "C" void kernel_launch(void* const* d_in, const int* in_sizes, int n_in,
                              void* d_out, int out_size)
{
    const float* X  = (const float*)d_in[0];   // (B, T, I)
    const float* Wi = (const float*)d_in[1];   // (B, O, I)
    const int* obs  = (const int*)d_in[2];     // (NOBS,)
    float* out      = (float*)d_out;           // (B, T, NOBS)

    gemm_g<<<dim3(Tt / 128, Tt / 128, Bb), 256>>>(X);
    gemm_d<<<dim3(Oo / 128, Tt / 128, Bb), 256>>>(X, Wi);
    scan_kernel<<<dim3(Oo / 128, Bb), 128>>>(obs, out);
}

// round 6
// speedup vs baseline: 3.6755x; 1.4351x over previous
#include <cuda_runtime.h>
#include <cuda_bf16.h>
#include <cstdint>

#define Bb   64
#define Tt   256
#define Ii   512
#define Oo   512
#define NOBS 128
#define ETA  0.01f
#define CH   32
#define NCH  (Tt / CH)

typedef unsigned long long u64;

// ---- scratch (static __device__, no allocs) ----
__device__ float G_buf[Bb * Tt * Tt];
__device__ float D_buf[Bb * Tt * Oo];
__device__ float U_buf[Bb * Tt * Oo];
__device__ __align__(16) __nv_bfloat16 Xhi_g[Bb * Tt * Ii];
__device__ __align__(16) __nv_bfloat16 Xlo_g[Bb * Tt * Ii];
__device__ __align__(16) __nv_bfloat16 Whi_g[Bb * Oo * Ii];
__device__ __align__(16) __nv_bfloat16 Wlo_g[Bb * Oo * Ii];

// ---- packed f32x2 helpers ----
__device__ __forceinline__ u64 pack2(float x, float y) {
    u64 r; asm("mov.b64 %0, {%1, %2};" : "=l"(r) : "f"(x), "f"(y)); return r;
}
__device__ __forceinline__ void unpack2(u64 v, float& x, float& y) {
    asm("mov.b64 {%0, %1}, %2;" : "=f"(x), "=f"(y) : "l"(v));
}
__device__ __forceinline__ u64 ffma2(u64 a, u64 b, u64 c) {
    u64 d; asm("fma.rn.f32x2 %0, %1, %2, %3;" : "=l"(d) : "l"(a), "l"(b), "l"(c)); return d;
}

// ---- mma.sync helpers (sm_80-era path; compiles for plain sm_100) ----
__device__ __forceinline__ uint32_t smem_u32(const void* p) {
    uint32_t a;
    asm("{ .reg .u64 t; cvta.to.shared.u64 t, %1; cvt.u32.u64 %0, t; }" : "=r"(a) : "l"(p));
    return a;
}
__device__ __forceinline__ void ldsm4(uint32_t addr, uint32_t r[4]) {
    asm volatile("ldmatrix.sync.aligned.m8n8.x4.shared.b16 {%0,%1,%2,%3}, [%4];"
                 : "=r"(r[0]), "=r"(r[1]), "=r"(r[2]), "=r"(r[3]) : "r"(addr));
}
__device__ __forceinline__ void mma16816(float c[4], const uint32_t a[4],
                                         uint32_t b0, uint32_t b1) {
    asm volatile("mma.sync.aligned.m16n8k16.row.col.f32.bf16.bf16.f32 "
                 "{%0,%1,%2,%3}, {%4,%5,%6,%7}, {%8,%9}, {%0,%1,%2,%3};"
                 : "+f"(c[0]), "+f"(c[1]), "+f"(c[2]), "+f"(c[3])
                 : "r"(a[0]), "r"(a[1]), "r"(a[2]), "r"(a[3]), "r"(b0), "r"(b1));
}

#define SWZ(x) ((x) ^ (((x) >> 3) & 0x70))

// ============================================================
// bf16 hi/lo split conversion
// ============================================================
__device__ __forceinline__ void split_store(const float* __restrict__ src,
                                            __nv_bfloat16* __restrict__ hi,
                                            __nv_bfloat16* __restrict__ lo, int i)
{
    float4 v = reinterpret_cast<const float4*>(src)[i];
    __nv_bfloat16 h0 = __float2bfloat16(v.x), h1 = __float2bfloat16(v.y);
    __nv_bfloat16 h2 = __float2bfloat16(v.z), h3 = __float2bfloat16(v.w);
    __nv_bfloat16 l0 = __float2bfloat16(v.x - __bfloat162float(h0));
    __nv_bfloat16 l1 = __float2bfloat16(v.y - __bfloat162float(h1));
    __nv_bfloat16 l2 = __float2bfloat16(v.z - __bfloat162float(h2));
    __nv_bfloat16 l3 = __float2bfloat16(v.w - __bfloat162float(h3));
    reinterpret_cast<__nv_bfloat162*>(hi)[2 * i]     = __nv_bfloat162(h0, h1);
    reinterpret_cast<__nv_bfloat162*>(hi)[2 * i + 1] = __nv_bfloat162(h2, h3);
    reinterpret_cast<__nv_bfloat162*>(lo)[2 * i]     = __nv_bfloat162(l0, l1);
    reinterpret_cast<__nv_bfloat162*>(lo)[2 * i + 1] = __nv_bfloat162(l2, l3);
}

__global__ void __launch_bounds__(256)
split_x(const float* __restrict__ X)
{
    int i = blockIdx.x * 256 + threadIdx.x;
    if (i < Bb * Tt * Ii / 4) split_store(X, Xhi_g, Xlo_g, i);
}

__global__ void __launch_bounds__(256)
split_w(const float* __restrict__ W)
{
    int i = blockIdx.x * 256 + threadIdx.x;
    if (i < Bb * Oo * Ii / 4) split_store(W, Whi_g, Wlo_g, i);
}

// ============================================================
// mma.sync bf16 3-term-split GEMM, 128x128 tile/CTA, K=512, NT.
// smem: Ahi/Alo/Bhi/Blo, each 128 rows x 64 bf16 (128 B rows, SW128).
// 8 warps = 2(m) x 4(n); warp tile 64x32.
// ============================================================
#define KC      64
#define NKC     (Ii / KC)     // 8
#define SM_TILE 16384
#define SM_TOTAL (4 * SM_TILE)

template<int M, int N, bool TRI>
__device__ __forceinline__ void gemm_core(const __nv_bfloat16* __restrict__ AH,
                                          const __nv_bfloat16* __restrict__ AL,
                                          const __nv_bfloat16* __restrict__ BH,
                                          const __nv_bfloat16* __restrict__ BL,
                                          float* __restrict__ Cg)
{
    const int nx = blockIdx.x, my = blockIdx.y, b = blockIdx.z;
    if (TRI && my > nx) return;

    extern __shared__ __align__(1024) char smem[];
    const uint32_t sb = smem_u32(smem);
    const int tid = threadIdx.x;
    const int wid = tid >> 5;
    const int l   = tid & 31;

    const int warp_m = wid & 1;        // 0..1 (64-row slab)
    const int warp_n = wid >> 1;       // 0..3 (32-col slab)

    const __nv_bfloat16* gbase[4];
    gbase[0] = AH + ((size_t)b * M + my * 128) * Ii;
    gbase[1] = AL + ((size_t)b * M + my * 128) * Ii;
    gbase[2] = BH + ((size_t)b * N + nx * 128) * Ii;
    gbase[3] = BL + ((size_t)b * N + nx * 128) * Ii;

    const uint32_t As_hi = sb;
    const uint32_t As_lo = sb + SM_TILE;
    const uint32_t Bs_hi = sb + 2 * SM_TILE;
    const uint32_t Bs_lo = sb + 3 * SM_TILE;

    // ldmatrix per-lane addressing (SW128: xor mask reduces to r<<4)
    const int g = l >> 3, r = l & 7;
    const uint32_t aoff = (uint32_t)(warp_m * 64 + (g & 1) * 8 + r) * 128;
    const uint32_t akb  = (uint32_t)((g >> 1) * 16);
    const uint32_t boff = (uint32_t)(warp_n * 32 + (g >> 1) * 8 + r) * 128;
    const uint32_t bkb  = (uint32_t)((g & 1) * 16);
    const uint32_t lxor = (uint32_t)(r << 4);

    float c[4][4][4];
    #pragma unroll
    for (int mt = 0; mt < 4; mt++)
        #pragma unroll
        for (int nt = 0; nt < 4; nt++)
            #pragma unroll
            for (int q = 0; q < 4; q++) c[mt][nt][q] = 0.0f;

    for (int ck = 0; ck < NKC; ck++) {
        __syncthreads();   // previous compute done reading smem
        // ---- stage chunk ck: 4 arrays x 128 rows x 8 x 16B units ----
        const int koff = ck * KC;
        #pragma unroll
        for (int i = 0; i < 16; i++) {
            const int u   = tid + 256 * i;       // 0..4095
            const int arr = u >> 10;
            const int rem = u & 1023;
            const int rw  = rem >> 3;
            const int un  = rem & 7;
            const float4 v = *reinterpret_cast<const float4*>(
                gbase[arr] + (size_t)rw * Ii + koff + un * 8);
            *reinterpret_cast<float4*>(smem + arr * SM_TILE + SWZ(rw * 128 + un * 16)) = v;
        }
        __syncthreads();

        // ---- compute: 4 k16 steps ----
        #pragma unroll
        for (int ks = 0; ks < 4; ks++) {
            const uint32_t kb = (uint32_t)(ks * 32);

            // B frags: bh/bl [nt][2]
            uint32_t bh[4][2], bl[4][2];
            #pragma unroll
            for (int nt2 = 0; nt2 < 2; nt2++) {
                uint32_t t4[4];
                const uint32_t badd = boff + nt2 * 2048 + ((kb + bkb) ^ lxor);
                ldsm4(Bs_hi + badd, t4);
                bh[2 * nt2][0] = t4[0]; bh[2 * nt2][1] = t4[1];
                bh[2 * nt2 + 1][0] = t4[2]; bh[2 * nt2 + 1][1] = t4[3];
                ldsm4(Bs_lo + badd, t4);
                bl[2 * nt2][0] = t4[0]; bl[2 * nt2][1] = t4[1];
                bl[2 * nt2 + 1][0] = t4[2]; bl[2 * nt2 + 1][1] = t4[3];
            }

            #pragma unroll
            for (int mt = 0; mt < 4; mt++) {
                const uint32_t aadd = aoff + mt * 2048 + ((kb + akb) ^ lxor);
                uint32_t a4[4];
                ldsm4(As_hi + aadd, a4);
                #pragma unroll
                for (int nt = 0; nt < 4; nt++) {
                    mma16816(c[mt][nt], a4, bh[nt][0], bh[nt][1]);
                    mma16816(c[mt][nt], a4, bl[nt][0], bl[nt][1]);
                }
                ldsm4(As_lo + aadd, a4);
                #pragma unroll
                for (int nt = 0; nt < 4; nt++)
                    mma16816(c[mt][nt], a4, bh[nt][0], bh[nt][1]);
            }
        }
    }

    // ---- epilogue: direct fragment stores (full 32B sectors) ----
    float* Crow = Cg + ((size_t)b * M + my * 128) * N + nx * 128;
    const int qr = l >> 2, qc = l & 3;
    #pragma unroll
    for (int mt = 0; mt < 4; mt++) {
        const int m0 = warp_m * 64 + mt * 16;
        #pragma unroll
        for (int nt = 0; nt < 4; nt++) {
            const int n0 = warp_n * 32 + nt * 8 + 2 * qc;
            *reinterpret_cast<float2*>(&Crow[(size_t)(m0 + qr) * N + n0]) =
                make_float2(c[mt][nt][0], c[mt][nt][1]);
            *reinterpret_cast<float2*>(&Crow[(size_t)(m0 + qr + 8) * N + n0]) =
                make_float2(c[mt][nt][2], c[mt][nt][3]);
        }
    }
}

__global__ void __launch_bounds__(256, 2)
gemm_g_k() { gemm_core<Tt, Tt, true>(Xhi_g, Xlo_g, Xhi_g, Xlo_g, G_buf); }

__global__ void __launch_bounds__(256, 2)
gemm_d_k() { gemm_core<Tt, Oo, false>(Xhi_g, Xlo_g, Whi_g, Wlo_g, D_buf); }

// ============================================================
// Scan: one thread per (b, o) row.
//   pre_t = P_{t-1} * ( d_t + sum_{j<t} u_j * G[j][t] )
// ============================================================
__global__ void __launch_bounds__(128, 4)
scan_kernel(const int* __restrict__ obs, float* __restrict__ out)
{
    __shared__ __align__(16) float Gs[Tt * CH];
    __shared__ float y_s[CH * 128];

    const int tid  = threadIdx.x;
    const int rg   = blockIdx.x;
    const int b    = blockIdx.y;
    const int orow = rg * 128 + tid;

    const int  slot_o    = obs[tid];
    const bool have_slot = ((slot_o >> 7) == rg);
    const int  slot_lrow = slot_o & 127;

    const float* Gb   = G_buf + (size_t)b * Tt * Tt;
    const float* Db   = D_buf + (size_t)b * Tt * Oo + orow;
    float*       Ub   = U_buf + (size_t)b * Tt * Oo + orow;
    float*       outb = out   + (size_t)b * Tt * NOBS;

    float P = 1.0f;
    float uc[CH];

    for (int c = 0; c < NCH; c++) {
        const int t0   = c * CH;
        const int rows = t0 + CH;

        __syncthreads();
        for (int i = tid; i < rows * CH; i += 128) {
            const int j = i >> 5, tl = i & 31;
            Gs[i] = Gb[j * Tt + t0 + tl];
        }
        __syncthreads();

        u64 hacc[CH / 2];
        #pragma unroll
        for (int q = 0; q < CH / 2; q++) hacc[q] = 0;
        for (int j = 0; j < t0; j++) {
            const float uj = Ub[j * Oo];
            const u64   u2 = pack2(uj, uj);
            const ulonglong2* grow = (const ulonglong2*)&Gs[j * CH];
            #pragma unroll
            for (int q = 0; q < CH / 4; q++) {
                ulonglong2 gg = grow[q];
                hacc[2 * q]     = ffma2(u2, gg.x, hacc[2 * q]);
                hacc[2 * q + 1] = ffma2(u2, gg.y, hacc[2 * q + 1]);
            }
        }
        float H[CH];
        #pragma unroll
        for (int q = 0; q < CH / 2; q++) unpack2(hacc[q], H[2 * q], H[2 * q + 1]);

        #pragma unroll
        for (int tl = 0; tl < CH; tl++) {
            float S = H[tl];
            #pragma unroll
            for (int jl = 0; jl < tl; jl++)
                S = fmaf(uc[jl], Gs[(t0 + jl) * CH + tl], S);
            const float d   = Db[(t0 + tl) * Oo];
            const float pre = P * (d + S);
            const float y   = 1.0f / (1.0f + __expf(-pre));
            const float c1  = 1.0f - ETA * y * y;
            P *= c1;
            const float u = __fdividef(ETA * y, P);
            uc[tl] = u;
            Ub[(t0 + tl) * Oo]  = u;
            y_s[tl * 128 + tid] = y;
        }
        __syncthreads();

        if (have_slot) {
            #pragma unroll 4
            for (int tl = 0; tl < CH; tl++)
                outb[(t0 + tl) * NOBS + tid] = y_s[tl * 128 + slot_lrow];
        }
    }
}

extern "C" void kernel_launch(void* const* d_in, const int* in_sizes, int n_in,
                              void* d_out, int out_size)
{
    const float* X  = (const float*)d_in[0];
    const float* Wi = (const float*)d_in[1];
    const int* obs  = (const int*)d_in[2];
    float* out      = (float*)d_out;

    cudaFuncSetAttribute(gemm_g_k, cudaFuncAttributeMaxDynamicSharedMemorySize, SM_TOTAL);
    cudaFuncSetAttribute(gemm_d_k, cudaFuncAttributeMaxDynamicSharedMemorySize, SM_TOTAL);

    const int nX4 = Bb * Tt * Ii / 4;
    const int nW4 = Bb * Oo * Ii / 4;
    split_x<<<(nX4 + 255) / 256, 256>>>(X);
    split_w<<<(nW4 + 255) / 256, 256>>>(Wi);

    gemm_g_k<<<dim3(Tt / 128, Tt / 128, Bb), 256, SM_TOTAL>>>();
    gemm_d_k<<<dim3(Oo / 128, Tt / 128, Bb), 256, SM_TOTAL>>>();

    scan_kernel<<<dim3(Oo / 128, Bb), 128>>>(obs, out);
}

// round 7
// speedup vs baseline: 4.7204x; 1.2843x over previous
#include <cuda_runtime.h>
#include <cuda_bf16.h>
#include <cstdint>

#define Bb   64
#define Tt   256
#define Ii   512
#define Oo   512
#define NOBS 128
#define ETA  0.01f
#define CH   32
#define NCH  (Tt / CH)

typedef unsigned long long u64;

// ---- scratch (static __device__, no allocs) ----
__device__ float G_buf[Bb * Tt * Tt];
__device__ float D_buf[Bb * Tt * Oo];
__device__ float U_buf[Bb * Tt * Oo];
__device__ __align__(16) __nv_bfloat16 Xhi_g[Bb * Tt * Ii];
__device__ __align__(16) __nv_bfloat16 Xlo_g[Bb * Tt * Ii];
__device__ __align__(16) __nv_bfloat16 Whi_g[Bb * Oo * Ii];
__device__ __align__(16) __nv_bfloat16 Wlo_g[Bb * Oo * Ii];

// ---- packed f32x2 helpers ----
__device__ __forceinline__ u64 pack2(float x, float y) {
    u64 r; asm("mov.b64 %0, {%1, %2};" : "=l"(r) : "f"(x), "f"(y)); return r;
}
__device__ __forceinline__ void unpack2(u64 v, float& x, float& y) {
    asm("mov.b64 {%0, %1}, %2;" : "=f"(x), "=f"(y) : "l"(v));
}
__device__ __forceinline__ u64 ffma2(u64 a, u64 b, u64 c) {
    u64 d; asm("fma.rn.f32x2 %0, %1, %2, %3;" : "=l"(d) : "l"(a), "l"(b), "l"(c)); return d;
}

// ---- mma.sync / cp.async helpers ----
__device__ __forceinline__ uint32_t smem_u32(const void* p) {
    uint32_t a;
    asm("{ .reg .u64 t; cvta.to.shared.u64 t, %1; cvt.u32.u64 %0, t; }" : "=r"(a) : "l"(p));
    return a;
}
__device__ __forceinline__ void ldsm4(uint32_t addr, uint32_t r[4]) {
    asm volatile("ldmatrix.sync.aligned.m8n8.x4.shared.b16 {%0,%1,%2,%3}, [%4];"
                 : "=r"(r[0]), "=r"(r[1]), "=r"(r[2]), "=r"(r[3]) : "r"(addr));
}
__device__ __forceinline__ void mma16816(float c[4], const uint32_t a[4],
                                         uint32_t b0, uint32_t b1) {
    asm volatile("mma.sync.aligned.m16n8k16.row.col.f32.bf16.bf16.f32 "
                 "{%0,%1,%2,%3}, {%4,%5,%6,%7}, {%8,%9}, {%0,%1,%2,%3};"
                 : "+f"(c[0]), "+f"(c[1]), "+f"(c[2]), "+f"(c[3])
                 : "r"(a[0]), "r"(a[1]), "r"(a[2]), "r"(a[3]), "r"(b0), "r"(b1));
}
#define CP_ASYNC16(dst, src) asm volatile("cp.async.cg.shared.global [%0], [%1], 16;" :: "r"(dst), "l"(src))
#define CP_COMMIT()          asm volatile("cp.async.commit_group;" ::: "memory")
#define CP_WAIT(n)           asm volatile("cp.async.wait_group %0;" :: "n"(n) : "memory")

#define SWZ(x) ((x) ^ (((x) >> 3) & 0x70))

// ============================================================
// bf16 hi/lo split conversion
// ============================================================
__device__ __forceinline__ void split_store(const float* __restrict__ src,
                                            __nv_bfloat16* __restrict__ hi,
                                            __nv_bfloat16* __restrict__ lo, int i)
{
    float4 v = reinterpret_cast<const float4*>(src)[i];
    __nv_bfloat16 h0 = __float2bfloat16(v.x), h1 = __float2bfloat16(v.y);
    __nv_bfloat16 h2 = __float2bfloat16(v.z), h3 = __float2bfloat16(v.w);
    __nv_bfloat16 l0 = __float2bfloat16(v.x - __bfloat162float(h0));
    __nv_bfloat16 l1 = __float2bfloat16(v.y - __bfloat162float(h1));
    __nv_bfloat16 l2 = __float2bfloat16(v.z - __bfloat162float(h2));
    __nv_bfloat16 l3 = __float2bfloat16(v.w - __bfloat162float(h3));
    reinterpret_cast<__nv_bfloat162*>(hi)[2 * i]     = __nv_bfloat162(h0, h1);
    reinterpret_cast<__nv_bfloat162*>(hi)[2 * i + 1] = __nv_bfloat162(h2, h3);
    reinterpret_cast<__nv_bfloat162*>(lo)[2 * i]     = __nv_bfloat162(l0, l1);
    reinterpret_cast<__nv_bfloat162*>(lo)[2 * i + 1] = __nv_bfloat162(l2, l3);
}

__global__ void __launch_bounds__(256)
split_x(const float* __restrict__ X)
{
    int i = blockIdx.x * 256 + threadIdx.x;
    if (i < Bb * Tt * Ii / 4) split_store(X, Xhi_g, Xlo_g, i);
}

__global__ void __launch_bounds__(256)
split_w(const float* __restrict__ W)
{
    int i = blockIdx.x * 256 + threadIdx.x;
    if (i < Bb * Oo * Ii / 4) split_store(W, Whi_g, Wlo_g, i);
}

// ============================================================
// mma.sync bf16 3-term-split GEMM, 128x128 tile/CTA, K=512, NT,
// 2-stage cp.async pipeline. smem: 2 stages x 4 tiles x 16 KB = 128 KB.
// 8 warps = 2(m) x 4(n); warp tile 64x32.
// ============================================================
#define KC       64
#define NKC      (Ii / KC)       // 8
#define SM_TILE  16384
#define SM_STAGE (4 * SM_TILE)   // 64 KB
#define SM_TOTAL (2 * SM_STAGE)  // 128 KB

template<int M, int N, bool TRI>
__device__ __forceinline__ void gemm_core(const __nv_bfloat16* __restrict__ AH,
                                          const __nv_bfloat16* __restrict__ AL,
                                          const __nv_bfloat16* __restrict__ BH,
                                          const __nv_bfloat16* __restrict__ BL,
                                          float* __restrict__ Cg)
{
    const int nx = blockIdx.x, my = blockIdx.y, b = blockIdx.z;
    if (TRI && my > nx) return;

    extern __shared__ __align__(1024) char smem[];
    const uint32_t sb = smem_u32(smem);
    const int tid = threadIdx.x;
    const int wid = tid >> 5;
    const int l   = tid & 31;

    const int warp_m = wid & 1;
    const int warp_n = wid >> 1;

    const __nv_bfloat16* gbase[4];
    gbase[0] = AH + ((size_t)b * M + my * 128) * Ii;
    gbase[1] = AL + ((size_t)b * M + my * 128) * Ii;
    gbase[2] = BH + ((size_t)b * N + nx * 128) * Ii;
    gbase[3] = BL + ((size_t)b * N + nx * 128) * Ii;

    // per-thread staging pattern: 16 units of 16 B
    int  s_arr[16], s_rw[16], s_un[16];
    uint32_t s_dst[16];
    #pragma unroll
    for (int i = 0; i < 16; i++) {
        const int u = tid + 256 * i;
        s_arr[i] = u >> 10;
        const int rem = u & 1023;
        s_rw[i] = rem >> 3;
        s_un[i] = rem & 7;
        s_dst[i] = (uint32_t)(s_arr[i] * SM_TILE + SWZ(s_rw[i] * 128 + s_un[i] * 16));
    }

    // ldmatrix per-lane addressing (SW128: xor mask reduces to r<<4)
    const int g = l >> 3, r = l & 7;
    const uint32_t aoff = (uint32_t)(warp_m * 64 + (g & 1) * 8 + r) * 128;
    const uint32_t akb  = (uint32_t)((g >> 1) * 16);
    const uint32_t boff = (uint32_t)(warp_n * 32 + (g >> 1) * 8 + r) * 128;
    const uint32_t bkb  = (uint32_t)((g & 1) * 16);
    const uint32_t lxor = (uint32_t)(r << 4);

    float c[4][4][4];
    #pragma unroll
    for (int mt = 0; mt < 4; mt++)
        #pragma unroll
        for (int nt = 0; nt < 4; nt++)
            #pragma unroll
            for (int q = 0; q < 4; q++) c[mt][nt][q] = 0.0f;

    // ---- prologue: stage chunk 0 into buf 0 ----
    #pragma unroll
    for (int i = 0; i < 16; i++) {
        const __nv_bfloat16* src = gbase[s_arr[i]] + (size_t)s_rw[i] * Ii + s_un[i] * 8;
        CP_ASYNC16(sb + s_dst[i], src);
    }
    CP_COMMIT();

    for (int ck = 0; ck < NKC; ck++) {
        const uint32_t buf = sb + (uint32_t)((ck & 1) * SM_STAGE);

        if (ck + 1 < NKC) {
            const uint32_t nbuf = (uint32_t)(((ck + 1) & 1) * SM_STAGE);
            const int koff = (ck + 1) * KC;
            #pragma unroll
            for (int i = 0; i < 16; i++) {
                const __nv_bfloat16* src =
                    gbase[s_arr[i]] + (size_t)s_rw[i] * Ii + koff + s_un[i] * 8;
                CP_ASYNC16(sb + nbuf + s_dst[i], src);
            }
            CP_COMMIT();
            CP_WAIT(1);
        } else {
            CP_WAIT(0);
        }
        __syncthreads();

        const uint32_t As_hi = buf;
        const uint32_t As_lo = buf + SM_TILE;
        const uint32_t Bs_hi = buf + 2 * SM_TILE;
        const uint32_t Bs_lo = buf + 3 * SM_TILE;

        #pragma unroll
        for (int ks = 0; ks < 4; ks++) {
            const uint32_t kb = (uint32_t)(ks * 32);

            uint32_t bh[4][2], bl[4][2];
            #pragma unroll
            for (int nt2 = 0; nt2 < 2; nt2++) {
                uint32_t t4[4];
                const uint32_t badd = boff + nt2 * 2048 + ((kb + bkb) ^ lxor);
                ldsm4(Bs_hi + badd, t4);
                bh[2 * nt2][0] = t4[0]; bh[2 * nt2][1] = t4[1];
                bh[2 * nt2 + 1][0] = t4[2]; bh[2 * nt2 + 1][1] = t4[3];
                ldsm4(Bs_lo + badd, t4);
                bl[2 * nt2][0] = t4[0]; bl[2 * nt2][1] = t4[1];
                bl[2 * nt2 + 1][0] = t4[2]; bl[2 * nt2 + 1][1] = t4[3];
            }

            #pragma unroll
            for (int mt = 0; mt < 4; mt++) {
                const uint32_t aadd = aoff + mt * 2048 + ((kb + akb) ^ lxor);
                uint32_t a4[4];
                ldsm4(As_hi + aadd, a4);
                #pragma unroll
                for (int nt = 0; nt < 4; nt++) {
                    mma16816(c[mt][nt], a4, bh[nt][0], bh[nt][1]);
                    mma16816(c[mt][nt], a4, bl[nt][0], bl[nt][1]);
                }
                ldsm4(As_lo + aadd, a4);
                #pragma unroll
                for (int nt = 0; nt < 4; nt++)
                    mma16816(c[mt][nt], a4, bh[nt][0], bh[nt][1]);
            }
        }
        __syncthreads();   // compute on buf done before it is refilled
    }

    // ---- epilogue: direct fragment stores ----
    float* Crow = Cg + ((size_t)b * M + my * 128) * N + nx * 128;
    const int qr = l >> 2, qc = l & 3;
    #pragma unroll
    for (int mt = 0; mt < 4; mt++) {
        const int m0 = warp_m * 64 + mt * 16;
        #pragma unroll
        for (int nt = 0; nt < 4; nt++) {
            const int n0 = warp_n * 32 + nt * 8 + 2 * qc;
            *reinterpret_cast<float2*>(&Crow[(size_t)(m0 + qr) * N + n0]) =
                make_float2(c[mt][nt][0], c[mt][nt][1]);
            *reinterpret_cast<float2*>(&Crow[(size_t)(m0 + qr + 8) * N + n0]) =
                make_float2(c[mt][nt][2], c[mt][nt][3]);
        }
    }
}

__global__ void __launch_bounds__(256, 1)
gemm_g_k() { gemm_core<Tt, Tt, true>(Xhi_g, Xlo_g, Xhi_g, Xlo_g, G_buf); }

__global__ void __launch_bounds__(256, 1)
gemm_d_k() { gemm_core<Tt, Oo, false>(Xhi_g, Xlo_g, Whi_g, Wlo_g, D_buf); }

// ============================================================
// Scan: one thread per (b, o) row.
//   pre_t = P_{t-1} * ( d_t + sum_{j<t} u_j * G[j][t] )
// History loop unrolled x8 with batched u prefetch (MLP=8).
// ============================================================
__global__ void __launch_bounds__(128, 4)
scan_kernel(const int* __restrict__ obs, float* __restrict__ out)
{
    __shared__ __align__(16) float Gs[Tt * CH];
    __shared__ float y_s[CH * 128];

    const int tid  = threadIdx.x;
    const int rg   = blockIdx.x;
    const int b    = blockIdx.y;
    const int orow = rg * 128 + tid;

    const int  slot_o    = obs[tid];
    const bool have_slot = ((slot_o >> 7) == rg);
    const int  slot_lrow = slot_o & 127;

    const float* Gb   = G_buf + (size_t)b * Tt * Tt;
    const float* Db   = D_buf + (size_t)b * Tt * Oo + orow;
    float*       Ub   = U_buf + (size_t)b * Tt * Oo + orow;
    float*       outb = out   + (size_t)b * Tt * NOBS;

    float P = 1.0f;
    float uc[CH];

    for (int c = 0; c < NCH; c++) {
        const int t0   = c * CH;
        const int rows = t0 + CH;

        __syncthreads();
        for (int i = tid; i < rows * CH; i += 128) {
            const int j = i >> 5, tl = i & 31;
            Gs[i] = Gb[j * Tt + t0 + tl];
        }
        __syncthreads();

        u64 hacc[CH / 2];
        #pragma unroll
        for (int q = 0; q < CH / 2; q++) hacc[q] = 0;

        for (int j = 0; j < t0; j += 8) {       // t0 is a multiple of 32
            float up[8];
            #pragma unroll
            for (int q = 0; q < 8; q++) up[q] = Ub[(j + q) * Oo];
            #pragma unroll
            for (int q = 0; q < 8; q++) {
                const u64 u2 = pack2(up[q], up[q]);
                const ulonglong2* grow = (const ulonglong2*)&Gs[(j + q) * CH];
                #pragma unroll
                for (int p = 0; p < CH / 4; p++) {
                    ulonglong2 gg = grow[p];
                    hacc[2 * p]     = ffma2(u2, gg.x, hacc[2 * p]);
                    hacc[2 * p + 1] = ffma2(u2, gg.y, hacc[2 * p + 1]);
                }
            }
        }
        float H[CH];
        #pragma unroll
        for (int q = 0; q < CH / 2; q++) unpack2(hacc[q], H[2 * q], H[2 * q + 1]);

        #pragma unroll
        for (int tl = 0; tl < CH; tl++) {
            float S = H[tl];
            #pragma unroll
            for (int jl = 0; jl < tl; jl++)
                S = fmaf(uc[jl], Gs[(t0 + jl) * CH + tl], S);
            const float d   = Db[(t0 + tl) * Oo];
            const float pre = P * (d + S);
            const float y   = 1.0f / (1.0f + __expf(-pre));
            const float c1  = 1.0f - ETA * y * y;
            P *= c1;
            const float u = __fdividef(ETA * y, P);
            uc[tl] = u;
            Ub[(t0 + tl) * Oo]  = u;
            y_s[tl * 128 + tid] = y;
        }
        __syncthreads();

        if (have_slot) {
            #pragma unroll 4
            for (int tl = 0; tl < CH; tl++)
                outb[(t0 + tl) * NOBS + tid] = y_s[tl * 128 + slot_lrow];
        }
    }
}

extern "C" void kernel_launch(void* const* d_in, const int* in_sizes, int n_in,
                              void* d_out, int out_size)
{
    const float* X  = (const float*)d_in[0];
    const float* Wi = (const float*)d_in[1];
    const int* obs  = (const int*)d_in[2];
    float* out      = (float*)d_out;

    cudaFuncSetAttribute(gemm_g_k, cudaFuncAttributeMaxDynamicSharedMemorySize, SM_TOTAL);
    cudaFuncSetAttribute(gemm_d_k, cudaFuncAttributeMaxDynamicSharedMemorySize, SM_TOTAL);

    const int nX4 = Bb * Tt * Ii / 4;
    const int nW4 = Bb * Oo * Ii / 4;
    split_x<<<(nX4 + 255) / 256, 256>>>(X);
    split_w<<<(nW4 + 255) / 256, 256>>>(Wi);

    gemm_g_k<<<dim3(Tt / 128, Tt / 128, Bb), 256, SM_TOTAL>>>();
    gemm_d_k<<<dim3(Oo / 128, Tt / 128, Bb), 256, SM_TOTAL>>>();

    scan_kernel<<<dim3(Oo / 128, Bb), 128>>>(obs, out);
}

// round 10
// speedup vs baseline: 6.4231x; 1.3607x over previous
#include <cuda_runtime.h>
#include <cuda_bf16.h>
#include <cstdint>

#define Bb   64
#define Tt   256
#define Ii   512
#define Oo   512
#define NOBS 128
#define ETA  0.01f
#define CH   32
#define NCH  (Tt / CH)

typedef unsigned long long u64;

// ---- scratch (static __device__, no allocs) ----
__device__ __align__(16) float G_buf[Bb * Tt * Tt];
__device__ __align__(16) float D_buf[Bb * Tt * Oo];
__device__ __align__(16) float U_buf[Bb * Tt * Oo];
__device__ __align__(16) __nv_bfloat16 Xhi_g[Bb * Tt * Ii];
__device__ __align__(16) __nv_bfloat16 Xlo_g[Bb * Tt * Ii];
__device__ __align__(16) __nv_bfloat16 Whi_g[Bb * Oo * Ii];
__device__ __align__(16) __nv_bfloat16 Wlo_g[Bb * Oo * Ii];

// ---- packed f32x2 helpers ----
__device__ __forceinline__ u64 pack2(float x, float y) {
    u64 r; asm("mov.b64 %0, {%1, %2};" : "=l"(r) : "f"(x), "f"(y)); return r;
}
__device__ __forceinline__ void unpack2(u64 v, float& x, float& y) {
    asm("mov.b64 {%0, %1}, %2;" : "=f"(x), "=f"(y) : "l"(v));
}
__device__ __forceinline__ u64 ffma2(u64 a, u64 b, u64 c) {
    u64 d; asm("fma.rn.f32x2 %0, %1, %2, %3;" : "=l"(d) : "l"(a), "l"(b), "l"(c)); return d;
}

// ---- mma.sync / cp.async helpers ----
__device__ __forceinline__ uint32_t smem_u32(const void* p) {
    uint32_t a;
    asm("{ .reg .u64 t; cvta.to.shared.u64 t, %1; cvt.u32.u64 %0, t; }" : "=r"(a) : "l"(p));
    return a;
}
__device__ __forceinline__ void ldsm4(uint32_t addr, uint32_t r[4]) {
    asm volatile("ldmatrix.sync.aligned.m8n8.x4.shared.b16 {%0,%1,%2,%3}, [%4];"
                 : "=r"(r[0]), "=r"(r[1]), "=r"(r[2]), "=r"(r[3]) : "r"(addr));
}
__device__ __forceinline__ void mma16816(float c[4], const uint32_t a[4],
                                         uint32_t b0, uint32_t b1) {
    asm volatile("mma.sync.aligned.m16n8k16.row.col.f32.bf16.bf16.f32 "
                 "{%0,%1,%2,%3}, {%4,%5,%6,%7}, {%8,%9}, {%0,%1,%2,%3};"
                 : "+f"(c[0]), "+f"(c[1]), "+f"(c[2]), "+f"(c[3])
                 : "r"(a[0]), "r"(a[1]), "r"(a[2]), "r"(a[3]), "r"(b0), "r"(b1));
}
#define CP_ASYNC16(dst, src) asm volatile("cp.async.cg.shared.global [%0], [%1], 16;" :: "r"(dst), "l"(src))
#define CP_COMMIT()          asm volatile("cp.async.commit_group;" ::: "memory")
#define CP_WAIT(n)           asm volatile("cp.async.wait_group %0;" :: "n"(n) : "memory")

#define SWZ(x) ((x) ^ (((x) >> 3) & 0x70))

// ============================================================
// bf16 hi/lo split conversion
// ============================================================
__device__ __forceinline__ void split_store(const float* __restrict__ src,
                                            __nv_bfloat16* __restrict__ hi,
                                            __nv_bfloat16* __restrict__ lo, int i)
{
    float4 v = reinterpret_cast<const float4*>(src)[i];
    __nv_bfloat16 h0 = __float2bfloat16(v.x), h1 = __float2bfloat16(v.y);
    __nv_bfloat16 h2 = __float2bfloat16(v.z), h3 = __float2bfloat16(v.w);
    __nv_bfloat16 l0 = __float2bfloat16(v.x - __bfloat162float(h0));
    __nv_bfloat16 l1 = __float2bfloat16(v.y - __bfloat162float(h1));
    __nv_bfloat16 l2 = __float2bfloat16(v.z - __bfloat162float(h2));
    __nv_bfloat16 l3 = __float2bfloat16(v.w - __bfloat162float(h3));
    reinterpret_cast<__nv_bfloat162*>(hi)[2 * i]     = __nv_bfloat162(h0, h1);
    reinterpret_cast<__nv_bfloat162*>(hi)[2 * i + 1] = __nv_bfloat162(h2, h3);
    reinterpret_cast<__nv_bfloat162*>(lo)[2 * i]     = __nv_bfloat162(l0, l1);
    reinterpret_cast<__nv_bfloat162*>(lo)[2 * i + 1] = __nv_bfloat162(l2, l3);
}

__global__ void __launch_bounds__(256)
split_x(const float* __restrict__ X)
{
    int i = blockIdx.x * 256 + threadIdx.x;
    if (i < Bb * Tt * Ii / 4) split_store(X, Xhi_g, Xlo_g, i);
}

__global__ void __launch_bounds__(256)
split_w(const float* __restrict__ W)
{
    int i = blockIdx.x * 256 + threadIdx.x;
    if (i < Bb * Oo * Ii / 4) split_store(W, Whi_g, Wlo_g, i);
}

// ============================================================
// mma.sync bf16 3-term-split GEMM (unchanged from R7: 417 us run)
// ============================================================
#define KC       64
#define NKC      (Ii / KC)
#define SM_TILE  16384
#define SM_STAGE (4 * SM_TILE)
#define SM_TOTAL (2 * SM_STAGE)

template<int M, int N, bool TRI>
__device__ __forceinline__ void gemm_core(const __nv_bfloat16* __restrict__ AH,
                                          const __nv_bfloat16* __restrict__ AL,
                                          const __nv_bfloat16* __restrict__ BH,
                                          const __nv_bfloat16* __restrict__ BL,
                                          float* __restrict__ Cg)
{
    const int nx = blockIdx.x, my = blockIdx.y, b = blockIdx.z;
    if (TRI && my > nx) return;

    extern __shared__ __align__(1024) char smem[];
    const uint32_t sb = smem_u32(smem);
    const int tid = threadIdx.x;
    const int wid = tid >> 5;
    const int l   = tid & 31;

    const int warp_m = wid & 1;
    const int warp_n = wid >> 1;

    const __nv_bfloat16* gbase[4];
    gbase[0] = AH + ((size_t)b * M + my * 128) * Ii;
    gbase[1] = AL + ((size_t)b * M + my * 128) * Ii;
    gbase[2] = BH + ((size_t)b * N + nx * 128) * Ii;
    gbase[3] = BL + ((size_t)b * N + nx * 128) * Ii;

    int  s_arr[16], s_rw[16], s_un[16];
    uint32_t s_dst[16];
    #pragma unroll
    for (int i = 0; i < 16; i++) {
        const int u = tid + 256 * i;
        s_arr[i] = u >> 10;
        const int rem = u & 1023;
        s_rw[i] = rem >> 3;
        s_un[i] = rem & 7;
        s_dst[i] = (uint32_t)(s_arr[i] * SM_TILE + SWZ(s_rw[i] * 128 + s_un[i] * 16));
    }

    const int g = l >> 3, r = l & 7;
    const uint32_t aoff = (uint32_t)(warp_m * 64 + (g & 1) * 8 + r) * 128;
    const uint32_t akb  = (uint32_t)((g >> 1) * 16);
    const uint32_t boff = (uint32_t)(warp_n * 32 + (g >> 1) * 8 + r) * 128;
    const uint32_t bkb  = (uint32_t)((g & 1) * 16);
    const uint32_t lxor = (uint32_t)(r << 4);

    float c[4][4][4];
    #pragma unroll
    for (int mt = 0; mt < 4; mt++)
        #pragma unroll
        for (int nt = 0; nt < 4; nt++)
            #pragma unroll
            for (int q = 0; q < 4; q++) c[mt][nt][q] = 0.0f;

    #pragma unroll
    for (int i = 0; i < 16; i++) {
        const __nv_bfloat16* src = gbase[s_arr[i]] + (size_t)s_rw[i] * Ii + s_un[i] * 8;
        CP_ASYNC16(sb + s_dst[i], src);
    }
    CP_COMMIT();

    for (int ck = 0; ck < NKC; ck++) {
        const uint32_t buf = sb + (uint32_t)((ck & 1) * SM_STAGE);

        if (ck + 1 < NKC) {
            const uint32_t nbuf = (uint32_t)(((ck + 1) & 1) * SM_STAGE);
            const int koff = (ck + 1) * KC;
            #pragma unroll
            for (int i = 0; i < 16; i++) {
                const __nv_bfloat16* src =
                    gbase[s_arr[i]] + (size_t)s_rw[i] * Ii + koff + s_un[i] * 8;
                CP_ASYNC16(sb + nbuf + s_dst[i], src);
            }
            CP_COMMIT();
            CP_WAIT(1);
        } else {
            CP_WAIT(0);
        }
        __syncthreads();

        const uint32_t As_hi = buf;
        const uint32_t As_lo = buf + SM_TILE;
        const uint32_t Bs_hi = buf + 2 * SM_TILE;
        const uint32_t Bs_lo = buf + 3 * SM_TILE;

        #pragma unroll
        for (int ks = 0; ks < 4; ks++) {
            const uint32_t kb = (uint32_t)(ks * 32);

            uint32_t bh[4][2], bl[4][2];
            #pragma unroll
            for (int nt2 = 0; nt2 < 2; nt2++) {
                uint32_t t4[4];
                const uint32_t badd = boff + nt2 * 2048 + ((kb + bkb) ^ lxor);
                ldsm4(Bs_hi + badd, t4);
                bh[2 * nt2][0] = t4[0]; bh[2 * nt2][1] = t4[1];
                bh[2 * nt2 + 1][0] = t4[2]; bh[2 * nt2 + 1][1] = t4[3];
                ldsm4(Bs_lo + badd, t4);
                bl[2 * nt2][0] = t4[0]; bl[2 * nt2][1] = t4[1];
                bl[2 * nt2 + 1][0] = t4[2]; bl[2 * nt2 + 1][1] = t4[3];
            }

            #pragma unroll
            for (int mt = 0; mt < 4; mt++) {
                const uint32_t aadd = aoff + mt * 2048 + ((kb + akb) ^ lxor);
                uint32_t a4[4];
                ldsm4(As_hi + aadd, a4);
                #pragma unroll
                for (int nt = 0; nt < 4; nt++) {
                    mma16816(c[mt][nt], a4, bh[nt][0], bh[nt][1]);
                    mma16816(c[mt][nt], a4, bl[nt][0], bl[nt][1]);
                }
                ldsm4(As_lo + aadd, a4);
                #pragma unroll
                for (int nt = 0; nt < 4; nt++)
                    mma16816(c[mt][nt], a4, bh[nt][0], bh[nt][1]);
            }
        }
        __syncthreads();
    }

    float* Crow = Cg + ((size_t)b * M + my * 128) * N + nx * 128;
    const int qr = l >> 2, qc = l & 3;
    #pragma unroll
    for (int mt = 0; mt < 4; mt++) {
        const int m0 = warp_m * 64 + mt * 16;
        #pragma unroll
        for (int nt = 0; nt < 4; nt++) {
            const int n0 = warp_n * 32 + nt * 8 + 2 * qc;
            *reinterpret_cast<float2*>(&Crow[(size_t)(m0 + qr) * N + n0]) =
                make_float2(c[mt][nt][0], c[mt][nt][1]);
            *reinterpret_cast<float2*>(&Crow[(size_t)(m0 + qr + 8) * N + n0]) =
                make_float2(c[mt][nt][2], c[mt][nt][3]);
        }
    }
}

__global__ void __launch_bounds__(256, 1)
gemm_g_k() { gemm_core<Tt, Tt, true>(Xhi_g, Xlo_g, Xhi_g, Xlo_g, G_buf); }

__global__ void __launch_bounds__(256, 1)
gemm_d_k() { gemm_core<Tt, Oo, false>(Xhi_g, Xlo_g, Whi_g, Wlo_g, D_buf); }

// ============================================================
// Scan v1.5 (R7 structure, static smem = 48 KB exactly):
//   + D values prefetched into regs before history (off serial chain)
//   + float4 G staging
// ============================================================
__global__ void __launch_bounds__(128, 4)
scan_kernel(const int* __restrict__ obs, float* __restrict__ out)
{
    __shared__ __align__(16) float Gs[Tt * CH];   // 32 KB
    __shared__ float y_s[CH * 128];               // 16 KB

    const int tid  = threadIdx.x;
    const int rg   = blockIdx.x;
    const int b    = blockIdx.y;
    const int orow = rg * 128 + tid;

    const int  slot_o    = obs[tid];
    const bool have_slot = ((slot_o >> 7) == rg);
    const int  slot_lrow = slot_o & 127;

    const float4* Gb4 = reinterpret_cast<const float4*>(G_buf + (size_t)b * Tt * Tt);
    const float* Db   = D_buf + (size_t)b * Tt * Oo + orow;
    float*       Ub   = U_buf + (size_t)b * Tt * Oo + orow;
    float*       outb = out   + (size_t)b * Tt * NOBS;

    float P = 1.0f;
    float uc[CH];

    for (int c = 0; c < NCH; c++) {
        const int t0   = c * CH;
        const int rows = t0 + CH;

        // prefetch this chunk's D values (independent LDGs, MLP=32;
        // hidden under the staging + history phases)
        float dv[CH];
        #pragma unroll
        for (int tl = 0; tl < CH; tl++) dv[tl] = Db[(t0 + tl) * Oo];

        __syncthreads();
        // stage Gs[j][tl] = G[b][j][t0+tl], j < rows, as float4
        // (t0 multiple of 32 -> float4-aligned source)
        {
            float4* dst = reinterpret_cast<float4*>(Gs);
            for (int i = tid; i < rows * 8; i += 128) {
                const int j = i >> 3, q = i & 7;
                dst[i] = Gb4[j * (Tt / 4) + t0 / 4 + q];
            }
        }
        __syncthreads();

        // ---- history: H[tl] = sum_{j<t0} u_j * G[j][t0+tl], MLP-8 u loads ----
        u64 hacc[CH / 2];
        #pragma unroll
        for (int q = 0; q < CH / 2; q++) hacc[q] = 0;

        for (int j = 0; j < t0; j += 8) {
            float up[8];
            #pragma unroll
            for (int q = 0; q < 8; q++) up[q] = Ub[(j + q) * Oo];
            #pragma unroll
            for (int q = 0; q < 8; q++) {
                const u64 u2 = pack2(up[q], up[q]);
                const ulonglong2* grow = (const ulonglong2*)&Gs[(j + q) * CH];
                #pragma unroll
                for (int p = 0; p < CH / 4; p++) {
                    ulonglong2 gg = grow[p];
                    hacc[2 * p]     = ffma2(u2, gg.x, hacc[2 * p]);
                    hacc[2 * p + 1] = ffma2(u2, gg.y, hacc[2 * p + 1]);
                }
            }
        }
        float H[CH];
        #pragma unroll
        for (int q = 0; q < CH / 2; q++) unpack2(hacc[q], H[2 * q], H[2 * q + 1]);

        // ---- serial 32-step diagonal (D already in regs) ----
        #pragma unroll
        for (int tl = 0; tl < CH; tl++) {
            float S = H[tl];
            #pragma unroll
            for (int jl = 0; jl < tl; jl++)
                S = fmaf(uc[jl], Gs[(t0 + jl) * CH + tl], S);
            const float pre = P * (dv[tl] + S);
            const float y   = 1.0f / (1.0f + __expf(-pre));
            const float c1  = 1.0f - ETA * y * y;
            P *= c1;
            const float u = __fdividef(ETA * y, P);
            uc[tl] = u;
            Ub[(t0 + tl) * Oo]  = u;
            y_s[tl * 128 + tid] = y;
        }
        __syncthreads();

        if (have_slot) {
            #pragma unroll 4
            for (int tl = 0; tl < CH; tl++)
                outb[(t0 + tl) * NOBS + tid] = y_s[tl * 128 + slot_lrow];
        }
    }
}

extern "C" void kernel_launch(void* const* d_in, const int* in_sizes, int n_in,
                              void* d_out, int out_size)
{
    const float* X  = (const float*)d_in[0];
    const float* Wi = (const float*)d_in[1];
    const int* obs  = (const int*)d_in[2];
    float* out      = (float*)d_out;

    cudaFuncSetAttribute(gemm_g_k, cudaFuncAttributeMaxDynamicSharedMemorySize, SM_TOTAL);
    cudaFuncSetAttribute(gemm_d_k, cudaFuncAttributeMaxDynamicSharedMemorySize, SM_TOTAL);

    const int nX4 = Bb * Tt * Ii / 4;
    const int nW4 = Bb * Oo * Ii / 4;
    split_x<<<(nX4 + 255) / 256, 256>>>(X);
    split_w<<<(nW4 + 255) / 256, 256>>>(Wi);

    gemm_g_k<<<dim3(Tt / 128, Tt / 128, Bb), 256, SM_TOTAL>>>();
    gemm_d_k<<<dim3(Oo / 128, Tt / 128, Bb), 256, SM_TOTAL>>>();

    scan_kernel<<<dim3(Oo / 128, Bb), 128>>>(obs, out);
}